// round 2
// baseline (speedup 1.0000x reference)
#include <cuda_runtime.h>
#include <cuda_bf16.h>
#include <stdint.h>

// Problem constants (fixed by the dataset)
#define LAYERS 2
#define NTRAIN 100000
#define DIM 512
#define BATCH 256
#define KNN 75
#define NCLS 10
#define NCALI 750

// ---------------- device scratch (no allocations allowed) ----------------
__device__ float g_scores[(size_t)LAYERS * BATCH * NTRAIN];  // 204.8 MB
__device__ float g_invn[LAYERS * NTRAIN];
__device__ int   g_counts[BATCH * NCLS];

// order-preserving map: float -> uint (ascending)
__device__ __forceinline__ unsigned fmap(float f) {
    unsigned u = __float_as_uint(f);
    return (u & 0x80000000u) ? ~u : (u | 0x80000000u);
}

// ---------------- kernel 1: train row inv-norms + zero counts ----------------
// warp per row; L*N = 200000 rows; 8 rows per 256-thread block.
__global__ void norm_kernel(const float* __restrict__ train) {
    if (blockIdx.x == 0) {
        for (int i = threadIdx.x; i < BATCH * NCLS; i += blockDim.x)
            g_counts[i] = 0;
    }
    int row = blockIdx.x * 8 + (threadIdx.x >> 5);
    int lane = threadIdx.x & 31;
    if (row >= LAYERS * NTRAIN) return;
    const float4* p = (const float4*)(train + (size_t)row * DIM);
    float s = 0.f;
#pragma unroll
    for (int j = 0; j < 4; ++j) {
        float4 v = p[lane + 32 * j];
        s += v.x * v.x + v.y * v.y + v.z * v.z + v.w * v.w;
    }
#pragma unroll
    for (int o = 16; o > 0; o >>= 1) s += __shfl_down_sync(0xffffffffu, s, o);
    if (lane == 0) g_invn[row] = 1.0f / sqrtf(s);
}

// ---------------- kernel 2: scores GEMM ----------------
// scores[l][b][n] = dot(q[l][b], t[l][n]) * invn[l][n]
#define BM 64
#define BN 64
#define BK 16
__global__ void __launch_bounds__(256) gemm_kernel(const float* __restrict__ qf,
                                                   const float* __restrict__ tf) {
    int l = blockIdx.z;
    const float* q = qf + (size_t)l * BATCH * DIM;
    const float* t = tf + (size_t)l * NTRAIN * DIM;
    const float* invn = g_invn + l * NTRAIN;
    float* out = g_scores + (size_t)l * BATCH * NTRAIN;

    int n0 = blockIdx.x * BN;
    int b0 = blockIdx.y * BM;

    __shared__ float As[BK][BM];      // [k][b]
    __shared__ float Bs[BK][BN];      // [k][n]

    int tid = threadIdx.x;
    int tx = tid & 15;   // n micro-tile
    int ty = tid >> 4;   // b micro-tile

    float acc[4][4] = {};

    int lrow = tid >> 2;          // 0..63
    int lcol = (tid & 3) * 4;     // 0,4,8,12

    for (int k0 = 0; k0 < DIM; k0 += BK) {
        // A tile: q[b0+lrow][k0+lcol .. +3] (b always in range: 256 % 64 == 0)
        float4 av = *(const float4*)&q[(size_t)(b0 + lrow) * DIM + k0 + lcol];
        As[lcol + 0][lrow] = av.x;
        As[lcol + 1][lrow] = av.y;
        As[lcol + 2][lrow] = av.z;
        As[lcol + 3][lrow] = av.w;
        // B tile: t[n0+lrow][k0+lcol .. +3] with tail guard
        int nr = n0 + lrow;
        float4 bv = make_float4(0.f, 0.f, 0.f, 0.f);
        if (nr < NTRAIN)
            bv = *(const float4*)&t[(size_t)nr * DIM + k0 + lcol];
        Bs[lcol + 0][lrow] = bv.x;
        Bs[lcol + 1][lrow] = bv.y;
        Bs[lcol + 2][lrow] = bv.z;
        Bs[lcol + 3][lrow] = bv.w;
        __syncthreads();
#pragma unroll
        for (int k = 0; k < BK; ++k) {
            float4 a = *(const float4*)&As[k][ty * 4];
            float4 b = *(const float4*)&Bs[k][tx * 4];
            float ar[4] = {a.x, a.y, a.z, a.w};
            float br[4] = {b.x, b.y, b.z, b.w};
#pragma unroll
            for (int i = 0; i < 4; ++i)
#pragma unroll
                for (int j = 0; j < 4; ++j)
                    acc[i][j] = fmaf(ar[i], br[j], acc[i][j]);
        }
        __syncthreads();
    }

    float inv[4];
#pragma unroll
    for (int j = 0; j < 4; ++j) {
        int nn = n0 + tx * 4 + j;
        inv[j] = (nn < NTRAIN) ? invn[nn] : 0.f;
    }
#pragma unroll
    for (int i = 0; i < 4; ++i) {
        int bb = b0 + ty * 4 + i;
        float* orow = out + (size_t)bb * NTRAIN;
#pragma unroll
        for (int j = 0; j < 4; ++j) {
            int nn = n0 + tx * 4 + j;
            if (nn < NTRAIN) orow[nn] = acc[i][j] * inv[j];
        }
    }
}

// ---------------- kernel 3: per-(l,b) top-75 radix select + label histogram ----------------
__global__ void __launch_bounds__(256) topk_kernel(const int* __restrict__ labels) {
    int row = blockIdx.x;               // 0..511 = l*BATCH + b
    int b = row & (BATCH - 1);
    const float* s = g_scores + (size_t)row * NTRAIN;
    int tid = threadIdx.x;
    const int BS = 256;

    __shared__ unsigned hist[256];
    __shared__ unsigned sh_prefix;
    __shared__ int sh_kneed;

    unsigned prefix = 0;
    int kneed = KNN;

    for (int pass = 0; pass < 4; ++pass) {
        int shift = 24 - 8 * pass;
        unsigned hi_mask = (pass == 0) ? 0u : (0xFFFFFFFFu << (shift + 8));
        for (int i = tid; i < 256; i += BS) hist[i] = 0;
        __syncthreads();
        for (int i = tid; i < NTRAIN; i += BS) {
            unsigned u = fmap(s[i]);
            if ((u & hi_mask) == prefix)
                atomicAdd(&hist[(u >> shift) & 255], 1u);
        }
        __syncthreads();
        if (tid == 0) {
            int cum = 0;
            int bsel = 0;
            for (int d = 255; d >= 0; --d) {
                int c = (int)hist[d];
                if (cum + c >= kneed) { bsel = d; break; }
                cum += c;
            }
            sh_prefix = prefix | ((unsigned)bsel << shift);
            sh_kneed = kneed - cum;
        }
        __syncthreads();
        prefix = sh_prefix;
        kneed = sh_kneed;
        __syncthreads();
    }

    unsigned u_th = prefix;   // threshold; take 'kneed' lowest-index elements == u_th

    __shared__ int cls[NCLS];
    __shared__ int tie_idx[1024];
    __shared__ int n_eq;
    if (tid < NCLS) cls[tid] = 0;
    if (tid == 0) n_eq = 0;
    __syncthreads();

    for (int i = tid; i < NTRAIN; i += BS) {
        unsigned u = fmap(s[i]);
        if (u > u_th) {
            atomicAdd(&cls[labels[i]], 1);
        } else if (u == u_th) {
            int p = atomicAdd(&n_eq, 1);
            if (p < 1024) tie_idx[p] = i;
        }
    }
    __syncthreads();

    if (tid == 0) {
        int m = n_eq < 1024 ? n_eq : 1024;
        int take = kneed < m ? kneed : m;
        for (int tki = 0; tki < take; ++tki) {
            int best = 0x7fffffff, bj = -1;
            for (int j = 0; j < m; ++j)
                if (tie_idx[j] < best) { best = tie_idx[j]; bj = j; }
            if (bj >= 0) {
                tie_idx[bj] = 0x7fffffff;
                cls[labels[best]]++;
            }
        }
    }
    __syncthreads();

    if (tid < NCLS) atomicAdd(&g_counts[b * NCLS + tid], cls[tid]);
}

// ---------------- kernel 4: conformal p-values, argmax, creds ----------------
__global__ void final_kernel(const int* __restrict__ cali, float* __restrict__ out) {
    __shared__ int cal[NCALI];
    for (int i = threadIdx.x; i < NCALI; i += blockDim.x) cal[i] = cali[i];
    __syncthreads();
    int b = threadIdx.x;
    if (b >= BATCH) return;
    float best = -1.f;
    int arg = 0;
    float pv[NCLS];
#pragma unroll
    for (int c = 0; c < NCLS; ++c) {
        int nc = LAYERS * KNN - g_counts[b * NCLS + c];
        int lo = 0, hi = NCALI;
        while (lo < hi) {
            int mid = (lo + hi) >> 1;
            if (cal[mid] < nc) lo = mid + 1; else hi = mid;
        }
        float p = (float)(NCALI - lo) / (float)NCALI;
        pv[c] = p;
        if (p > best) { best = p; arg = c; }
    }
#pragma unroll
    for (int c = 0; c < NCLS; ++c)
        out[b * NCLS + c] = (c == arg) ? pv[c] : 0.0f;
}

// ---------------- launch ----------------
extern "C" void kernel_launch(void* const* d_in, const int* in_sizes, int n_in,
                              void* d_out, int out_size) {
    const float* train = (const float*)d_in[0];
    const float* query = (const float*)d_in[1];
    const int* labels = (const int*)d_in[2];
    const int* cali = (const int*)d_in[3];
    float* out = (float*)d_out;

    norm_kernel<<<(LAYERS * NTRAIN + 7) / 8, 256>>>(train);

    dim3 ggrid((NTRAIN + BN - 1) / BN, BATCH / BM, LAYERS);
    gemm_kernel<<<ggrid, 256>>>(query, train);

    topk_kernel<<<LAYERS * BATCH, 256>>>(labels);

    final_kernel<<<1, 256>>>(cali, out);
}

// round 5
// speedup vs baseline: 1.6089x; 1.6089x over previous
#include <cuda_runtime.h>
#include <cuda_bf16.h>
#include <stdint.h>

// Problem constants (fixed by the dataset)
#define LAYERS 2
#define NTRAIN 100000
#define DIM 512
#define BATCH 256
#define KNN 75
#define NCLS 10
#define NCALI 750

// ---------------- device scratch (no allocations allowed) ----------------
__device__ float g_scores[(size_t)LAYERS * BATCH * NTRAIN];  // 204.8 MB
__device__ float g_invn[LAYERS * NTRAIN];
__device__ int   g_counts[BATCH * NCLS];

// order-preserving map: float -> uint (ascending)
__device__ __forceinline__ unsigned fmap(float f) {
    unsigned u = __float_as_uint(f);
    return (u & 0x80000000u) ? ~u : (u | 0x80000000u);
}

// ---------------- kernel 1: train row inv-norms + zero counts ----------------
__global__ void norm_kernel(const float* __restrict__ train) {
    if (blockIdx.x == 0) {
        for (int i = threadIdx.x; i < BATCH * NCLS; i += blockDim.x)
            g_counts[i] = 0;
    }
    int row = blockIdx.x * 8 + (threadIdx.x >> 5);
    int lane = threadIdx.x & 31;
    if (row >= LAYERS * NTRAIN) return;
    const float4* p = (const float4*)(train + (size_t)row * DIM);
    float s = 0.f;
#pragma unroll
    for (int j = 0; j < 4; ++j) {
        float4 v = p[lane + 32 * j];
        s += v.x * v.x + v.y * v.y + v.z * v.z + v.w * v.w;
    }
#pragma unroll
    for (int o = 16; o > 0; o >>= 1) s += __shfl_down_sync(0xffffffffu, s, o);
    if (lane == 0) g_invn[row] = 1.0f / sqrtf(s);
}

// ---------------- kernel 2: scores GEMM (128x128x8, double-buffered, 8x8 micro) ----------------
#define GBM 128
#define GBN 128
#define GBK 8
#define SPITCH 132   // padded smem row: conflict-free STS

__global__ void __launch_bounds__(256) gemm_kernel(const float* __restrict__ qf,
                                                   const float* __restrict__ tf) {
    int l = blockIdx.z;
    const float* q = qf + (size_t)l * BATCH * DIM;
    const float* t = tf + (size_t)l * NTRAIN * DIM;
    const float* invn = g_invn + l * NTRAIN;
    float* out = g_scores + (size_t)l * BATCH * NTRAIN;

    int n0 = blockIdx.x * GBN;
    int b0 = blockIdx.y * GBM;

    __shared__ float As[2][GBK][SPITCH];  // [buf][k][m]
    __shared__ float Bs[2][GBK][SPITCH];  // [buf][k][n]

    int tid = threadIdx.x;
    int tx = tid & 15;    // n micro dir
    int ty = tid >> 4;    // m micro dir

    int lr = tid >> 1;          // 0..127: tile row
    int lc = (tid & 1) * 4;     // 0 or 4: k offset

    const float* aptr = q + (size_t)(b0 + lr) * DIM + lc;
    int brow = n0 + lr;
    bool bvalid = brow < NTRAIN;
    const float* bptr = t + (size_t)brow * DIM + lc;

    float acc[8][8];
#pragma unroll
    for (int i = 0; i < 8; ++i)
#pragma unroll
        for (int j = 0; j < 8; ++j) acc[i][j] = 0.f;

    // prologue: tile 0
    {
        float4 av = *(const float4*)aptr;
        float4 bv = bvalid ? *(const float4*)bptr : make_float4(0.f, 0.f, 0.f, 0.f);
        As[0][lc + 0][lr] = av.x; As[0][lc + 1][lr] = av.y;
        As[0][lc + 2][lr] = av.z; As[0][lc + 3][lr] = av.w;
        Bs[0][lc + 0][lr] = bv.x; Bs[0][lc + 1][lr] = bv.y;
        Bs[0][lc + 2][lr] = bv.z; Bs[0][lc + 3][lr] = bv.w;
    }
    __syncthreads();

    const int NIT = DIM / GBK;  // 64
    for (int it = 0; it < NIT; ++it) {
        int buf = it & 1;
        float4 av2, bv2;
        if (it + 1 < NIT) {
            av2 = *(const float4*)(aptr + (it + 1) * GBK);
            bv2 = bvalid ? *(const float4*)(bptr + (it + 1) * GBK)
                         : make_float4(0.f, 0.f, 0.f, 0.f);
        }
#pragma unroll
        for (int k = 0; k < GBK; ++k) {
            float4 a0 = *(const float4*)&As[buf][k][ty * 4];
            float4 a1 = *(const float4*)&As[buf][k][ty * 4 + 64];
            float4 bq0 = *(const float4*)&Bs[buf][k][tx * 4];
            float4 bq1 = *(const float4*)&Bs[buf][k][tx * 4 + 64];
            float am[8] = {a0.x, a0.y, a0.z, a0.w, a1.x, a1.y, a1.z, a1.w};
            float bn[8] = {bq0.x, bq0.y, bq0.z, bq0.w, bq1.x, bq1.y, bq1.z, bq1.w};
#pragma unroll
            for (int i = 0; i < 8; ++i)
#pragma unroll
                for (int j = 0; j < 8; ++j)
                    acc[i][j] = fmaf(am[i], bn[j], acc[i][j]);
        }
        if (it + 1 < NIT) {
            int nb = buf ^ 1;
            As[nb][lc + 0][lr] = av2.x; As[nb][lc + 1][lr] = av2.y;
            As[nb][lc + 2][lr] = av2.z; As[nb][lc + 3][lr] = av2.w;
            Bs[nb][lc + 0][lr] = bv2.x; Bs[nb][lc + 1][lr] = bv2.y;
            Bs[nb][lc + 2][lr] = bv2.z; Bs[nb][lc + 3][lr] = bv2.w;
            __syncthreads();
        }
    }

    // epilogue: multiply by invn[n], store as guarded float4 (NTRAIN % 4 == 0)
#pragma unroll
    for (int jh = 0; jh < 2; ++jh) {
        int n = n0 + tx * 4 + jh * 64;
        if (n >= NTRAIN) continue;
        float4 iv = *(const float4*)&invn[n];
#pragma unroll
        for (int ih = 0; ih < 2; ++ih) {
#pragma unroll
            for (int i = 0; i < 4; ++i) {
                int r = b0 + ty * 4 + ih * 64 + i;
                float4 v;
                v.x = acc[ih * 4 + i][jh * 4 + 0] * iv.x;
                v.y = acc[ih * 4 + i][jh * 4 + 1] * iv.y;
                v.z = acc[ih * 4 + i][jh * 4 + 2] * iv.z;
                v.w = acc[ih * 4 + i][jh * 4 + 3] * iv.w;
                *(float4*)&out[(size_t)r * NTRAIN + n] = v;
            }
        }
    }
}

// ---------------- kernel 3: per-(l,b) top-75: 12-bit radix narrow + candidate pass ----------------
#define TKCAP 2048

__global__ void __launch_bounds__(256) topk_kernel(const int* __restrict__ labels) {
    int row = blockIdx.x;               // 0..511 = l*BATCH + b
    int b = row & (BATCH - 1);
    const float4* s4 = (const float4*)(g_scores + (size_t)row * NTRAIN);
    const int N4 = NTRAIN / 4;
    int tid = threadIdx.x;
    const int BS = 256;

    __shared__ unsigned hist[4096];
    __shared__ unsigned coarse[256];
    __shared__ unsigned sh_prefix;
    __shared__ int sh_kneed;
    __shared__ int sh_shift;
    __shared__ int sh_done;

    unsigned prefix = 0;
    unsigned mask = 0;
    int kneed = KNN;
    int shift = 20;

    // ---- narrowing loop: histogram 12 bits at a time until bin count <= TKCAP ----
    for (int level = 0; level < 4; ++level) {
        for (int i = tid; i < 4096; i += BS) hist[i] = 0;
        __syncthreads();
        for (int i = tid; i < N4; i += BS) {
            float4 v = s4[i];
            float vv[4] = {v.x, v.y, v.z, v.w};
#pragma unroll
            for (int c = 0; c < 4; ++c) {
                unsigned u = fmap(vv[c]);
                if ((u & mask) == prefix)
                    atomicAdd(&hist[(u >> shift) & 4095], 1u);
            }
        }
        __syncthreads();
        // coarse suffix structure: each thread sums its 16-bin chunk
        unsigned csum = 0;
#pragma unroll
        for (int j = 0; j < 16; ++j) csum += hist[tid * 16 + j];
        coarse[tid] = csum;
        __syncthreads();
        if (tid == 0) {
            int cum = 0;
            int bsel = 0;
            unsigned bcnt = 0;
            // scan chunks from top
            for (int ci = 255; ci >= 0; --ci) {
                int c = (int)coarse[ci];
                if (cum + c >= kneed) {
                    // scan bins within chunk from top
                    for (int bi = ci * 16 + 15; bi >= ci * 16; --bi) {
                        int h = (int)hist[bi];
                        if (cum + h >= kneed) { bsel = bi; bcnt = (unsigned)h; break; }
                        cum += h;
                    }
                    break;
                }
                cum += c;
            }
            sh_prefix = prefix | ((unsigned)bsel << shift);
            sh_kneed = kneed - cum;
            sh_done = (bcnt <= TKCAP) ? 1 : 0;
            sh_shift = shift;
        }
        __syncthreads();
        prefix = sh_prefix;
        kneed = sh_kneed;
        int done = sh_done;
        __syncthreads();
        mask |= (0xFFFu << shift);
        if (done || shift == 0) break;
        shift = (shift >= 12) ? shift - 12 : 0;
    }

    // bin = [T_lo, T_hi);  everything >= T_hi is definitely in top-K
    unsigned T_lo = prefix;
    unsigned long long T_hi = (unsigned long long)prefix + (1ull << shift);

    __shared__ int cls[NCLS];
    __shared__ unsigned cand_u[TKCAP];
    __shared__ int cand_i[TKCAP];
    __shared__ int n_eq;
    if (tid < NCLS) cls[tid] = 0;
    if (tid == 0) n_eq = 0;
    __syncthreads();

    for (int i = tid; i < N4; i += BS) {
        float4 v = s4[i];
        float vv[4] = {v.x, v.y, v.z, v.w};
#pragma unroll
        for (int c = 0; c < 4; ++c) {
            unsigned u = fmap(vv[c]);
            if ((unsigned long long)u >= T_hi) {
                atomicAdd(&cls[labels[4 * i + c]], 1);
            } else if (u >= T_lo) {
                int p = atomicAdd(&n_eq, 1);
                if (p < TKCAP) { cand_u[p] = u; cand_i[p] = 4 * i + c; }
            }
        }
    }
    __syncthreads();

    int m = n_eq;
    if (m <= TKCAP) {
        // exact rank among candidates: value desc, index asc; take rank < kneed
        for (int i = tid; i < m; i += BS) {
            unsigned ui = cand_u[i];
            int ii = cand_i[i];
            int rank = 0;
            for (int j = 0; j < m; ++j) {
                unsigned uj = cand_u[j];
                int ij = cand_i[j];
                rank += (uj > ui) || (uj == ui && ij < ii);
            }
            if (rank < kneed) atomicAdd(&cls[labels[ii]], 1);
        }
    } else if (tid == 0) {
        // degenerate fallback (shift==0, >TKCAP identical values): lowest indices win
        const float* s = g_scores + (size_t)row * NTRAIN;
        int taken = 0;
        for (int i = 0; i < NTRAIN && taken < kneed; ++i) {
            if (fmap(s[i]) == T_lo) { cls[labels[i]]++; taken++; }
        }
    }
    __syncthreads();

    if (tid < NCLS) atomicAdd(&g_counts[b * NCLS + tid], cls[tid]);
}

// ---------------- kernel 4: conformal p-values, argmax, creds ----------------
__global__ void final_kernel(const int* __restrict__ cali, float* __restrict__ out) {
    __shared__ int cal[NCALI];
    for (int i = threadIdx.x; i < NCALI; i += blockDim.x) cal[i] = cali[i];
    __syncthreads();
    int b = threadIdx.x;
    if (b >= BATCH) return;
    float best = -1.f;
    int arg = 0;
    float pv[NCLS];
#pragma unroll
    for (int c = 0; c < NCLS; ++c) {
        int nc = LAYERS * KNN - g_counts[b * NCLS + c];
        int lo = 0, hi = NCALI;
        while (lo < hi) {
            int mid = (lo + hi) >> 1;
            if (cal[mid] < nc) lo = mid + 1; else hi = mid;
        }
        float p = (float)(NCALI - lo) / (float)NCALI;
        pv[c] = p;
        if (p > best) { best = p; arg = c; }
    }
#pragma unroll
    for (int c = 0; c < NCLS; ++c)
        out[b * NCLS + c] = (c == arg) ? pv[c] : 0.0f;
}

// ---------------- launch ----------------
extern "C" void kernel_launch(void* const* d_in, const int* in_sizes, int n_in,
                              void* d_out, int out_size) {
    const float* train = (const float*)d_in[0];
    const float* query = (const float*)d_in[1];
    const int* labels = (const int*)d_in[2];
    const int* cali = (const int*)d_in[3];
    float* out = (float*)d_out;

    norm_kernel<<<(LAYERS * NTRAIN + 7) / 8, 256>>>(train);

    dim3 ggrid((NTRAIN + GBN - 1) / GBN, BATCH / GBM, LAYERS);
    gemm_kernel<<<ggrid, 256>>>(query, train);

    topk_kernel<<<LAYERS * BATCH, 256>>>(labels);

    final_kernel<<<1, 256>>>(cali, out);
}